// round 5
// baseline (speedup 1.0000x reference)
#include <cuda_runtime.h>
#include <cuda_bf16.h>

// diag-embed: out[i, j, k] = (j == k) ? x[i, j] : 0
// x: [8192, 176] fp32, out: [8192, 176, 176] fp32 (~1.015 GB of stores).
//
// R5: R4 shape frozen (1184 x 256 = 8 blocks/SM, branchless, __stcs,
// unroll 8). New: each thread handles an aligned PAIR of float4 chunks
// (32 B) per iteration. 44 chunks/row is even, so a pair never straddles a
// row -> one div/mod + one LDG serve 32 B instead of 16 B, halving the
// per-byte index/load instruction cost.

#define D_MODEL 176u
#define PPR 22u            // float4-PAIRS per output row (44/2)
#define BLOCKS 1184u       // 148 SMs * 8 blocks, perfectly balanced
#define THREADS 256u

__global__ __launch_bounds__(THREADS) void diag_embed_kernel(
        const float* __restrict__ x,
        float4* __restrict__ out,
        unsigned npairs) {
    const unsigned stride = BLOCKS * THREADS;
    unsigned p = blockIdx.x * THREADS + threadIdx.x;

    #pragma unroll 8
    for (; p < npairs; p += stride) {
        unsigned rowg = p / PPR;                 // 32-bit magic div
        unsigned qp   = p - rowg * PPR;          // pair index within row
        unsigned row  = rowg % D_MODEL;          // diag position in row

        // One L2-hot load covers both chunks of the pair.
        float xv = __ldg(x + rowg);

        unsigned c0 = qp * 8u;                   // first column of the pair
        float4 a, b;
        a.x = (c0      == row) ? xv : 0.f;
        a.y = (c0 + 1u == row) ? xv : 0.f;
        a.z = (c0 + 2u == row) ? xv : 0.f;
        a.w = (c0 + 3u == row) ? xv : 0.f;
        b.x = (c0 + 4u == row) ? xv : 0.f;
        b.y = (c0 + 5u == row) ? xv : 0.f;
        b.z = (c0 + 6u == row) ? xv : 0.f;
        b.w = (c0 + 7u == row) ? xv : 0.f;

        float4* dst = out + (size_t)p * 2u;
        __stcs(dst,     a);                      // adjacent 16B streaming stores
        __stcs(dst + 1, b);
    }
}

extern "C" void kernel_launch(void* const* d_in, const int* in_sizes, int n_in,
                              void* d_out, int out_size) {
    const float* x = (const float*)d_in[0];
    float4* out = (float4*)d_out;

    unsigned npairs = (unsigned)(out_size / 8);  // 31,719,424 32B pairs

    diag_embed_kernel<<<BLOCKS, THREADS>>>(x, out, npairs);
}

// round 6
// speedup vs baseline: 1.6217x; 1.6217x over previous
#include <cuda_runtime.h>
#include <cuda_bf16.h>

// diag-embed: out[i, j, k] = (j == k) ? x[i, j] : 0
// x: [8192, 176] fp32, out: [8192, 176, 176] fp32 (~1.015 GB of stores).
//
// R6: R4 shape frozen (1184 x 256, branchless selects, __stcs). Widening done
// at the WARP-TILE level to preserve coalescing (R5 broke it with per-lane
// stride-2): each warp owns 64 consecutive chunks/iter; lane l handles
// base+l and base+l+32. Second chunk's row/q derived from the first with a
// cheap carry fixup instead of a second div/mod.

#define D_MODEL 176u
#define CPR 44u            // float4 chunks per output row
#define BLOCKS 1184u       // 148 SMs * 8 blocks, perfectly balanced
#define THREADS 256u

__global__ __launch_bounds__(THREADS) void diag_embed_kernel(
        const float* __restrict__ x,
        float4* __restrict__ out,
        unsigned n4) {
    const unsigned lane   = threadIdx.x & 31u;
    const unsigned warp   = (blockIdx.x * THREADS + threadIdx.x) >> 5;
    const unsigned nwarps = (BLOCKS * THREADS) >> 5;
    const unsigned stride = nwarps * 64u;        // chunks per full sweep

    unsigned g0 = warp * 64u + lane;             // first chunk (lanes consecutive)

    #pragma unroll 4
    for (; g0 < n4; g0 += stride) {
        // ---- chunk A: full magic div/mod ----
        unsigned rowg0 = g0 / CPR;
        unsigned q0    = g0 - rowg0 * CPR;
        unsigned row0  = rowg0 % D_MODEL;

        // ---- chunk B = A + 32: derive indices with carry fixup ----
        unsigned g1    = g0 + 32u;
        unsigned qt    = q0 + 32u;
        unsigned carry = (qt >= CPR) ? 1u : 0u;
        unsigned q1    = qt - (carry ? CPR : 0u);
        unsigned rowg1 = rowg0 + carry;
        unsigned rt    = row0 + carry;
        unsigned row1  = (rt == D_MODEL) ? 0u : rt;

        float xv0 = __ldg(x + rowg0);            // both L1/L2-hot (x = 5.8 MB)
        float xv1 = __ldg(x + rowg1);

        unsigned c0 = q0 * 4u;
        float4 a;
        a.x = (c0      == row0) ? xv0 : 0.f;
        a.y = (c0 + 1u == row0) ? xv0 : 0.f;
        a.z = (c0 + 2u == row0) ? xv0 : 0.f;
        a.w = (c0 + 3u == row0) ? xv0 : 0.f;

        unsigned c1 = q1 * 4u;
        float4 b;
        b.x = (c1      == row1) ? xv1 : 0.f;
        b.y = (c1 + 1u == row1) ? xv1 : 0.f;
        b.z = (c1 + 2u == row1) ? xv1 : 0.f;
        b.w = (c1 + 3u == row1) ? xv1 : 0.f;

        __stcs(out + g0, a);                     // lanes consecutive -> coalesced
        if (g1 < n4) __stcs(out + g1, b);        // lanes consecutive -> coalesced
    }
}

extern "C" void kernel_launch(void* const* d_in, const int* in_sizes, int n_in,
                              void* d_out, int out_size) {
    const float* x = (const float*)d_in[0];
    float4* out = (float4*)d_out;

    unsigned n4 = (unsigned)(out_size / 4);      // 63,438,848 float4 chunks

    diag_embed_kernel<<<BLOCKS, THREADS>>>(x, out, n4);
}